// round 16
// baseline (speedup 1.0000x reference)
#include <cuda_runtime.h>
#include <cuda_bf16.h>
#include <cuda_fp16.h>
#include <cuda_fp8.h>
#include <math.h>
#include <stdint.h>

// Problem constants
#define N    8192
#define D_O  512
#define D_T  768

#define BM 128
#define BN 128
#define NBJ (N / BN)                 // 64 column-blocks
#define NT  (NBJ * (NBJ + 1) / 2)    // 2080 upper-tri tiles
#define NP  1056                     // sum over bi of ceil((64-bi)/2): tile PAIRS

// Arch-specific (sm_103a) feature gate: tcgen05 PTX only legal at compute_103a.
#if defined(__CUDA_ARCH__) && defined(__CUDA_ARCH_FEAT_SM103_ALL)
#define USE_TCGEN05 1
#else
#define USE_TCGEN05 0
#endif

#define SMEM_SWIZZLE_128B(b) ((b) ^ (((b) >> 3) & 0x70))

// ---------------------------------------------------------------------------
// Common helpers
// ---------------------------------------------------------------------------
__device__ __forceinline__ uint32_t smem_to_u32(const void* p) {
    uint32_t a;
    asm("{ .reg .u64 t; cvta.to.shared.u64 t, %1; cvt.u32.u64 %0, t; }" : "=r"(a) : "l"(p));
    return a;
}
__device__ __forceinline__ uint32_t pack_fp8x4(float v0, float v1, float v2, float v3) {
    __nv_fp8x2_storage_t lo = __nv_cvt_float2_to_fp8x2(make_float2(v0, v1),
                                                       __NV_SATFINITE, __NV_E4M3);
    __nv_fp8x2_storage_t hi = __nv_cvt_float2_to_fp8x2(make_float2(v2, v3),
                                                       __NV_SATFINITE, __NV_E4M3);
    return (uint32_t)lo | ((uint32_t)hi << 16);
}
__device__ __forceinline__ float2 fp8x2_to_float2(uint16_t v) {
    __half2_raw h2 = __nv_cvt_fp8x2_to_halfraw2((__nv_fp8x2_storage_t)v, __NV_E4M3);
    return __half22float2(*reinterpret_cast<__half2*>(&h2));
}
__device__ __forceinline__ __half2 fp8x2_to_half2(uint16_t v) {
    __half2_raw h2 = __nv_cvt_fp8x2_to_halfraw2((__nv_fp8x2_storage_t)v, __NV_E4M3);
    return *reinterpret_cast<__half2*>(&h2);
}
__device__ __forceinline__ float ex2f(float x) {
    float r;
    asm("ex2.approx.f32 %0, %1;" : "=f"(r) : "f"(x));
    return r;
}
#define EXP3_LOG2E 4.328085122666891f   // 3 * log2(e)

#define CP_ASYNC16(sa, ga) \
    asm volatile("cp.async.cg.shared.global [%0], [%1], 16;" :: "r"(sa), "l"(ga))
#define CP_COMMIT() asm volatile("cp.async.commit_group;" ::: "memory")
#define CP_WAIT(n)  asm volatile("cp.async.wait_group %0;" :: "n"(n) : "memory")

#if USE_TCGEN05
__device__ __forceinline__ uint32_t elect_one_pred() {
    uint32_t pred;
    asm volatile(
        "{\n\t.reg .pred p;\n\telect.sync _|p, 0xFFFFFFFF;\n\tselp.b32 %0, 1, 0, p;\n\t}"
        : "=r"(pred));
    return pred;
}

#define TCGEN05_ALLOC(smem_result_addr, nCols) \
    asm volatile("tcgen05.alloc.cta_group::1.sync.aligned.shared::cta.b32 [%0], %1;" \
        :: "r"((uint32_t)(smem_result_addr)), "r"((uint32_t)(nCols)) : "memory")
#define TCGEN05_DEALLOC(tmem_addr, nCols) \
    asm volatile("tcgen05.dealloc.cta_group::1.sync.aligned.b32 %0, %1;" \
        :: "r"(tmem_addr), "r"((uint32_t)(nCols)))
#define TCGEN05_RELINQUISH() \
    asm volatile("tcgen05.relinquish_alloc_permit.cta_group::1.sync.aligned;")
#define TCGEN05_COMMIT(mbar_smem_addr) \
    asm volatile("tcgen05.commit.cta_group::1.mbarrier::arrive::one.shared::cluster.b64 [%0];" \
        :: "r"((uint32_t)(mbar_smem_addr)) : "memory")
#define TCGEN05_FENCE_AFTER() \
    asm volatile("tcgen05.fence::after_thread_sync;" ::: "memory")
#define TCGEN05_WAIT_LD() \
    asm volatile("tcgen05.wait::ld.sync.aligned;" ::: "memory")
#define FENCE_PROXY_ASYNC_SHARED_CTA() \
    asm volatile("fence.proxy.async.shared::cta;" ::: "memory")
#define MBARRIER_INIT(mbar, count) \
    asm volatile("mbarrier.init.shared.b64 [%0], %1;" \
        :: "r"((uint32_t)(mbar)), "r"((uint32_t)(count)) : "memory")
#define MBARRIER_INVAL(mbar) \
    asm volatile("mbarrier.inval.shared.b64 [%0];" :: "r"((uint32_t)(mbar)) : "memory")

#define MBARRIER_WAIT_PARITY(mbar_smem_addr, phase_parity) do { \
    uint32_t _mbar = (uint32_t)(mbar_smem_addr); \
    uint32_t _parity = (uint32_t)(phase_parity); \
    uint32_t _done; \
    asm volatile( \
        "{\n\t.reg .pred p;\n\t" \
        "mbarrier.try_wait.parity.acquire.cta.shared::cta.b64 p, [%1], %2;\n\t" \
        "selp.b32 %0, 1, 0, p;\n\t}" \
        : "=r"(_done) : "r"(_mbar), "r"(_parity) : "memory"); \
    if (!_done) { \
        asm volatile( \
            "{\n\t.reg .pred P1;\n\t" \
            "WAIT_LOOP_%=:\n\t" \
            "mbarrier.try_wait.parity.acquire.cta.shared::cta.b64 P1, [%0], %1, 0x989680;\n\t" \
            "@P1 bra.uni WAIT_DONE_%=;\n\t" \
            "bra.uni WAIT_LOOP_%=;\n\t" \
            "WAIT_DONE_%=:\n\t}" \
            :: "r"(_mbar), "r"(_parity) : "memory"); \
    } \
} while(0)

#define TCGEN05_LD_32X32B_X32(r, tmem_addr) \
    asm volatile( \
        "tcgen05.ld.sync.aligned.32x32b.x32.b32 " \
        "{%0, %1, %2, %3, %4, %5, %6, %7, " \
        " %8, %9, %10, %11, %12, %13, %14, %15, " \
        " %16, %17, %18, %19, %20, %21, %22, %23, " \
        " %24, %25, %26, %27, %28, %29, %30, %31}, [%32];" \
        : "=r"((r)[0]),  "=r"((r)[1]),  "=r"((r)[2]),  "=r"((r)[3]), \
          "=r"((r)[4]),  "=r"((r)[5]),  "=r"((r)[6]),  "=r"((r)[7]), \
          "=r"((r)[8]),  "=r"((r)[9]),  "=r"((r)[10]), "=r"((r)[11]), \
          "=r"((r)[12]), "=r"((r)[13]), "=r"((r)[14]), "=r"((r)[15]), \
          "=r"((r)[16]), "=r"((r)[17]), "=r"((r)[18]), "=r"((r)[19]), \
          "=r"((r)[20]), "=r"((r)[21]), "=r"((r)[22]), "=r"((r)[23]), \
          "=r"((r)[24]), "=r"((r)[25]), "=r"((r)[26]), "=r"((r)[27]), \
          "=r"((r)[28]), "=r"((r)[29]), "=r"((r)[30]), "=r"((r)[31]) \
        : "r"(tmem_addr))

// FP8 (e4m3 x e4m3 -> f32) SS MMA, cta_group::1, kind::f8f6f4.
__device__ __forceinline__ void mma_f8_ss_cg1(
    uint32_t d_tmem, uint64_t a_desc, uint64_t b_desc, uint32_t idesc, bool en) {
    uint32_t e = en ? 1 : 0;
    asm volatile(
        "{\n\t.reg .pred p;\n\tsetp.ne.u32 p, %5, 0;\n\t"
        "tcgen05.mma.cta_group::1.kind::f8f6f4 [%0], %1, %2, %3, {%4, %4, %4, %4}, p;\n\t}"
        :: "r"(d_tmem), "l"(a_desc), "l"(b_desc), "r"(idesc), "r"(0u), "r"(e)
        : "memory");
}

static constexpr uint64_t SMEM_DESC_BASE_SW128 =
    (uint64_t(2) << 61) | (uint64_t(1) << 46) | (uint64_t(64) << 32) | (uint64_t(1) << 16);
#define MAKE_SMEM_DESC(base_addr) \
    (SMEM_DESC_BASE_SW128 | ((uint64_t)((base_addr) >> 4) & 0x3FFF))

// idesc: f32 accum (bit4), E4M3 A/B, N=128, M=128
static constexpr uint32_t MMA_IDESC_F8 =
    (1u << 4) | ((128u / 8) << 17) | ((128u / 16) << 24);
#endif // USE_TCGEN05

// Fallback fragment ops (legal PTX at .target sm_103; compile-only safety net)
__device__ __forceinline__ void ldmatrix_x4(uint32_t* r, uint32_t addr) {
    asm volatile("ldmatrix.sync.aligned.m8n8.x4.shared.b16 {%0,%1,%2,%3}, [%4];"
        : "=r"(r[0]), "=r"(r[1]), "=r"(r[2]), "=r"(r[3]) : "r"(addr));
}
__device__ __forceinline__ void mma_16816_bf16(float* c, const uint32_t* a, const uint32_t* b) {
    asm volatile(
        "mma.sync.aligned.m16n8k16.row.col.f32.bf16.bf16.f32 "
        "{%0,%1,%2,%3}, {%4,%5,%6,%7}, {%8,%9}, {%0,%1,%2,%3};"
        : "+f"(c[0]), "+f"(c[1]), "+f"(c[2]), "+f"(c[3])
        : "r"(a[0]), "r"(a[1]), "r"(a[2]), "r"(a[3]), "r"(b[0]), "r"(b[1]));
}

// ---------------------------------------------------------------------------
// Scratch (__device__ globals)
// ---------------------------------------------------------------------------
__device__ __align__(16) __nv_fp8_e4m3 g_x8[N * D_O];             // normalized, e4m3
__device__ __align__(16) __nv_fp8_e4m3 g_t8[N * D_T];
__device__ __align__(16) __nv_fp8_e4m3 g_sim8_o[(size_t)N * N];   // 64 MB, upper-tri
__device__ __align__(16) __nv_fp8_e4m3 g_sim8_t[(size_t)N * N];
__device__ float g_dpart[2][N * NBJ];
__device__ __align__(16) float2 g_EF[N];  // {E3 = 1/den_t^3, F = E3*(Lo - Lt)}
__device__ float g_losspart[NT];

// ---------------------------------------------------------------------------
// Warp-per-row L2-normalize (fp32 math) -> e4m3. 8 rows per 256-thread block.
// ---------------------------------------------------------------------------
__global__ void __launch_bounds__(256) normalize_kernel(
    const float* __restrict__ mo, const float* __restrict__ tg) {
    const int gw    = blockIdx.x * 8 + (threadIdx.x >> 5);
    const int which = (gw >= N);
    const int row   = which ? (gw - N) : gw;
    const int D     = which ? D_T : D_O;
    const int lane  = threadIdx.x & 31;
    const float4* xr4 = (const float4*)((which ? tg : mo) + (size_t)row * D);
    uint32_t* orow = (uint32_t*)((which ? g_t8 : g_x8) + (size_t)row * D);
    const int nseg = D >> 7;

    float4 rv[6];
    float ss = 0.f;
    #pragma unroll 6
    for (int s = 0; s < nseg; s++) {
        float4 v = xr4[lane + s * 32];
        rv[s] = v;
        ss += v.x * v.x + v.y * v.y + v.z * v.z + v.w * v.w;
    }
    #pragma unroll
    for (int o = 16; o; o >>= 1) ss += __shfl_xor_sync(0xffffffffu, ss, o);
    const float sc = 1.0f / fmaxf(sqrtf(ss), 1e-8f);

    #pragma unroll 6
    for (int s = 0; s < nseg; s++) {
        float4 v = rv[s];
        orow[lane + s * 32] = pack_fp8x4(v.x * sc, v.y * sc, v.z * sc, v.w * sc);
    }
}

// ---------------------------------------------------------------------------
// Triangular decode: t -> (bi, bj), bi <= bj
// ---------------------------------------------------------------------------
__device__ __forceinline__ void tri_decode(int t, int& bi, int& bj) {
    int b = (int)(NBJ + 0.5f - sqrtf((NBJ + 0.5f) * (NBJ + 0.5f) - 2.0f * (float)t));
    if (b < 0) b = 0;
    if (b > NBJ - 1) b = NBJ - 1;
    #define TRI_START(x) ((x) * (2 * NBJ - (x) + 1) / 2)
    while (b > 0 && TRI_START(b) > t) b--;
    while (b < NBJ - 1 && TRI_START(b + 1) <= t) b++;
    bi = b;
    bj = b + (t - TRI_START(b));
    #undef TRI_START
}

// Pair decode: p in [0, NP) -> (bi, bj1)
__device__ __forceinline__ void pair_decode(int p, int& bi, int& bj1) {
    int rem = p;
    int b = 0;
    while (true) {
        int cnt = (NBJ - b + 1) >> 1;
        if (rem < cnt) break;
        rem -= cnt;
        b++;
    }
    bi = b;
    bj1 = b + 2 * rem;
}

// ---------------------------------------------------------------------------
// cp.async loaders: 128 rows x 128 e4m3 (16 KB) per matrix per chunk, SW128.
// ---------------------------------------------------------------------------
__device__ __forceinline__ void load_one(
    const __nv_fp8_e4m3* Xb, int D, int c, uint32_t smX, int tid)
{
    #pragma unroll
    for (int s = 0; s < 4; s++) {
        int seg = tid + s * 256;
        int row = seg >> 3;
        int sc  = seg & 7;
        uint32_t off = SMEM_SWIZZLE_128B((uint32_t)(row * 128 + sc * 16));
        CP_ASYNC16(smX + off, Xb + (size_t)row * D + c * 128 + sc * 16);
    }
}
__device__ __forceinline__ void load_three(
    const __nv_fp8_e4m3* Ab, const __nv_fp8_e4m3* B1, const __nv_fp8_e4m3* B2,
    int D, int c, uint32_t smA, uint32_t smB1, uint32_t smB2, bool act2, int tid)
{
    #pragma unroll
    for (int s = 0; s < 4; s++) {
        int seg = tid + s * 256;
        int row = seg >> 3;
        int sc  = seg & 7;
        uint32_t off = SMEM_SWIZZLE_128B((uint32_t)(row * 128 + sc * 16));
        const size_t g = (size_t)row * D + c * 128 + sc * 16;
        CP_ASYNC16(smA + off, Ab + g);
        CP_ASYNC16(smB1 + off, B1 + g);
        if (act2) CP_ASYNC16(smB2 + off, B2 + g);
    }
}

// ---------------------------------------------------------------------------
// Full-tile epilogue store (fp8 sims) + column partials.
// stage2: 128x128 fp32 (stride 129).  bstage: 128 x 32 u32 (stride 33).
// ---------------------------------------------------------------------------
__device__ __forceinline__ void epilogue_store_and_cols_full(
    const float* stage2, const uint32_t* bstage, float (*scolp)[2],
    __nv_fp8_e4m3* simb, int bi, int bj, int tid)
{
    __nv_fp8_e4m3* dst = simb + (size_t)(bi * BM) * N + (size_t)bj * BN;
    #pragma unroll
    for (int p = 0; p < 16; p++) {
        int idx = p * 256 + tid;          // 4096 u32 per tile
        int rr = idx >> 5;
        int cw = idx & 31;
        ((uint32_t*)(dst + (size_t)rr * N))[cw] = bstage[rr * 33 + cw];
    }
    if (bi != bj) {
        const int cc   = tid & 127;
        const int part = tid >> 7;        // 2 parts x 64 rows
        float ec = 0.f;
        #pragma unroll 16
        for (int rr = 0; rr < 64; rr++)
            ec += stage2[(part * 64 + rr) * 129 + cc];
        scolp[cc][part] = ec;
    }
}

// ---------------------------------------------------------------------------
// Pair GEMM kernel (FP8): tiles (bi,bj1) and (bi,bj1+1), shared A load,
// 2-stage cp.async pipeline with split commits. Full-tile epilogue.
//   grid.x = 2*NP, which = blockIdx.x & 1
// ---------------------------------------------------------------------------
__global__ void __launch_bounds__(256, 2) gemm_tc_kernel() {
    const int which = blockIdx.x & 1;
    const int pidx  = blockIdx.x >> 1;
    const int D     = which ? D_T : D_O;
    const int NCH   = D >> 7;
    const __nv_fp8_e4m3* X = which ? g_t8 : g_x8;
    __nv_fp8_e4m3* simb    = which ? g_sim8_t : g_sim8_o;
    float* dpart           = g_dpart[which];

    extern __shared__ char dsm_raw[];
    __shared__ float spart[128][4];
    __shared__ float scolp[128][2];

    const uint32_t raw  = smem_to_u32(dsm_raw);
    const uint32_t base = (raw + 1023u) & ~1023u;
    char* sm = dsm_raw + (base - raw);
    float*    stage2 = (float*)sm;                 // full tile: 128x129 fp32 (66048 B)
    uint32_t* bstage = (uint32_t*)(sm + 66048);    // packed fp8x4: 128x33 u32 (16896 B)

    const int tid = threadIdx.x;
    const int wid = tid >> 5;
    const int lid = tid & 31;

    int bi, bj1;
    pair_decode(pidx, bi, bj1);
    const int bj2 = bj1 + 1;
    const bool act2 = (bj2 < NBJ);

    const __nv_fp8_e4m3* Ab  = X + (size_t)bi  * BM * D;
    const __nv_fp8_e4m3* B1b = X + (size_t)bj1 * BN * D;
    const __nv_fp8_e4m3* B2b = X + (size_t)(act2 ? bj2 : bj1) * BN * D;

#if USE_TCGEN05
    // ================= tcgen05: 2-stage pipeline, split commits ============
    __shared__ uint32_t s_tmem;
    __shared__ __align__(8) uint64_t s_mbar[2][2];

    if (wid == 0) {
        TCGEN05_ALLOC(smem_to_u32(&s_tmem), 256);
        TCGEN05_RELINQUISH();
    }
    if (tid == 0) {
        MBARRIER_INIT(smem_to_u32(&s_mbar[0][0]), 1);
        MBARRIER_INIT(smem_to_u32(&s_mbar[0][1]), 1);
        MBARRIER_INIT(smem_to_u32(&s_mbar[1][0]), 1);
        MBARRIER_INIT(smem_to_u32(&s_mbar[1][1]), 1);
    }
    __syncthreads();
    const uint32_t tmem = s_tmem;

    uint32_t smA[2], smB1[2], smB2[2];
    uint64_t adesc[2], b1desc[2], b2desc[2];
    #pragma unroll
    for (int s = 0; s < 2; s++) {
        smA[s]  = base + s * 49152u;
        smB1[s] = smA[s] + 16384u;
        smB2[s] = smA[s] + 32768u;
        adesc[s]  = MAKE_SMEM_DESC(smA[s]);
        b1desc[s] = MAKE_SMEM_DESC(smB1[s]);
        b2desc[s] = MAKE_SMEM_DESC(smB2[s]);
    }

    load_three(Ab, B1b, B2b, D, 0, smA[0], smB1[0], smB2[0], act2, tid); CP_COMMIT();
    load_three(Ab, B1b, B2b, D, 1, smA[1], smB1[1], smB2[1], act2, tid); CP_COMMIT();

    for (int c = 0; c < NCH; c++) {
        const int b = c & 1;
        if (c + 1 < NCH) CP_WAIT(1);
        else             CP_WAIT(0);
        FENCE_PROXY_ASYNC_SHARED_CTA();
        __syncthreads();

        if (wid == 0 && elect_one_pred()) {
            #pragma unroll
            for (int k = 0; k < 4; k++)
                mma_f8_ss_cg1(tmem, adesc[b] + k * 2, b1desc[b] + k * 2,
                              MMA_IDESC_F8, (c > 0) || (k > 0));
            TCGEN05_COMMIT(smem_to_u32(&s_mbar[b][0]));
            if (act2) {
                #pragma unroll
                for (int k = 0; k < 4; k++)
                    mma_f8_ss_cg1(tmem + 128, adesc[b] + k * 2, b2desc[b] + k * 2,
                                  MMA_IDESC_F8, (c > 0) || (k > 0));
            }
            TCGEN05_COMMIT(smem_to_u32(&s_mbar[b][1]));
        }
        if (c + 2 < NCH) {
            const int ph = (c >> 1) & 1;
            MBARRIER_WAIT_PARITY(smem_to_u32(&s_mbar[b][0]), ph);
            load_one(B1b, D, c + 2, smB1[b], tid);
            MBARRIER_WAIT_PARITY(smem_to_u32(&s_mbar[b][1]), ph);
            load_one(Ab, D, c + 2, smA[b], tid);
            if (act2) load_one(B2b, D, c + 2, smB2[b], tid);
            CP_COMMIT();
        }
    }
    {
        const int cl = NCH - 1;
        const int ph = (cl >> 1) & 1;
        MBARRIER_WAIT_PARITY(smem_to_u32(&s_mbar[cl & 1][1]), ph);
    }
    TCGEN05_FENCE_AFTER();
    __syncthreads();

    // ---- full-tile epilogue: both halves, then single store/col pass ----
    const int sub = wid & 3;
    const int cg  = wid >> 2;
    const int r   = sub * 32 + lid;
    const int gi  = bi * BM + r;

    const int ntile = act2 ? 2 : 1;
    for (int tt = 0; tt < ntile; tt++) {
        const int bj = bj1 + tt;
        const bool odg = (bi != bj);
        #pragma unroll
        for (int h = 0; h < 2; h++) {
            uint32_t dreg[32];
            TCGEN05_LD_32X32B_X32(dreg, tmem + tt * 128 + h * 64 + cg * 32);
            TCGEN05_WAIT_LD();

            const int c0  = h * 64 + cg * 32;     // tile-local col base
            const int gj0 = bj * BN + c0;
            float rs = 0.f;
            #pragma unroll
            for (int j = 0; j < 32; j += 4) {
                float v0 = __uint_as_float(dreg[j]);
                float v1 = __uint_as_float(dreg[j + 1]);
                float v2 = __uint_as_float(dreg[j + 2]);
                float v3 = __uint_as_float(dreg[j + 3]);
                float e0 = __expf(v0);
                float e1 = __expf(v1);
                float e2 = __expf(v2);
                float e3 = __expf(v3);
                if (gi == gj0 + j)     e0 = 0.f;
                if (gi == gj0 + j + 1) e1 = 0.f;
                if (gi == gj0 + j + 2) e2 = 0.f;
                if (gi == gj0 + j + 3) e3 = 0.f;
                rs += (e0 + e1) + (e2 + e3);
                if (odg) {
                    stage2[r * 129 + c0 + j]     = e0;
                    stage2[r * 129 + c0 + j + 1] = e1;
                    stage2[r * 129 + c0 + j + 2] = e2;
                    stage2[r * 129 + c0 + j + 3] = e3;
                }
                bstage[r * 33 + (c0 >> 2) + (j >> 2)] = pack_fp8x4(v0, v1, v2, v3);
            }
            spart[r][h * 2 + cg] = rs;
        }
        __syncthreads();

        epilogue_store_and_cols_full(stage2, bstage, scolp, simb, bi, bj, tid);
        __syncthreads();

        if (tid < 128) {
            float rsum = spart[tid][0] + spart[tid][1] + spart[tid][2] + spart[tid][3];
            dpart[(size_t)(bi * BM + tid) * NBJ + bj] = rsum;
            if (odg) {
                float csum = scolp[tid][0] + scolp[tid][1];
                dpart[(size_t)(bj * BN + tid) * NBJ + bi] = csum;
            }
        }
        __syncthreads();
    }

    if (tid == 0) {
        MBARRIER_INVAL(smem_to_u32(&s_mbar[0][0]));
        MBARRIER_INVAL(smem_to_u32(&s_mbar[0][1]));
        MBARRIER_INVAL(smem_to_u32(&s_mbar[1][0]));
        MBARRIER_INVAL(smem_to_u32(&s_mbar[1][1]));
    }
    __syncthreads();
    if (wid == 0) TCGEN05_DEALLOC(tmem, 256);
#else
    // ================= mma.sync fallback (compile-only safety net) =========
    const uint32_t smA0 = base;
    const uint32_t smB0 = base + 16384u;
    char* smc = sm;
    const int warp_m = wid & 3;
    const int warp_n = wid >> 2;
    const int NCH2 = D >> 6;

    const int ntile = act2 ? 2 : 1;
    for (int tt = 0; tt < ntile; tt++) {
        const int bj = bj1 + tt;
        const __nv_fp8_e4m3* Bb = X + (size_t)bj * BN * D;

        float c[2][8][4];
        #pragma unroll
        for (int mt = 0; mt < 2; mt++)
            #pragma unroll
            for (int nt = 0; nt < 8; nt++)
                #pragma unroll
                for (int q = 0; q < 4; q++) c[mt][nt][q] = 0.f;

        for (int ch = 0; ch < NCH2; ch++) {
            #pragma unroll
            for (int s = 0; s < 4; s++) {
                int seg = tid + s * 256;
                int row = seg >> 3;
                int sc  = seg & 7;
                const __nv_fp8_e4m3* pa = Ab + (size_t)row * D + ch * 64 + sc * 8;
                const __nv_fp8_e4m3* pb = Bb + (size_t)row * D + ch * 64 + sc * 8;
                __nv_bfloat16 at[8], bt[8];
                #pragma unroll
                for (int i = 0; i < 8; i++) {
                    at[i] = __float2bfloat16((float)pa[i]);
                    bt[i] = __float2bfloat16((float)pb[i]);
                }
                uint32_t off = SMEM_SWIZZLE_128B((uint32_t)(row * 128 + sc * 16));
                *(uint4*)(smc + off)         = *(uint4*)at;
                *(uint4*)(smc + 16384 + off) = *(uint4*)bt;
            }
            __syncthreads();

            #pragma unroll
            for (int ks = 0; ks < 4; ks++) {
                uint32_t a[2][4];
                #pragma unroll
                for (int mt = 0; mt < 2; mt++) {
                    int row  = warp_m * 32 + mt * 16 + (lid & 15);
                    int boff = ks * 32 + (lid >> 4) * 16;
                    ldmatrix_x4(a[mt], smA0 + SMEM_SWIZZLE_128B((uint32_t)(row * 128 + boff)));
                }
                uint32_t b[8][2];
                #pragma unroll
                for (int np = 0; np < 4; np++) {
                    int mat = lid >> 3;
                    int nt  = np * 2 + (mat >> 1);
                    int kh  = mat & 1;
                    int row  = warp_n * 64 + nt * 8 + (lid & 7);
                    int boff = ks * 32 + kh * 16;
                    uint32_t r4[4];
                    ldmatrix_x4(r4, smB0 + SMEM_SWIZZLE_128B((uint32_t)(row * 128 + boff)));
                    b[np * 2][0]     = r4[0];
                    b[np * 2][1]     = r4[1];
                    b[np * 2 + 1][0] = r4[2];
                    b[np * 2 + 1][1] = r4[3];
                }
                #pragma unroll
                for (int mt = 0; mt < 2; mt++)
                    #pragma unroll
                    for (int nt = 0; nt < 8; nt++)
                        mma_16816_bf16(c[mt][nt], a[mt], b[nt]);
            }
            __syncthreads();
        }

        #pragma unroll
        for (int mt = 0; mt < 2; mt++)
            #pragma unroll
            for (int nt = 0; nt < 8; nt++) {
                int r0  = warp_m * 32 + mt * 16 + (lid >> 2);
                int col = warp_n * 64 + nt * 8 + (lid & 3) * 2;
                stage2[r0 * 129 + col]           = c[mt][nt][0];
                stage2[r0 * 129 + col + 1]       = c[mt][nt][1];
                stage2[(r0 + 8) * 129 + col]     = c[mt][nt][2];
                stage2[(r0 + 8) * 129 + col + 1] = c[mt][nt][3];
            }
        __syncthreads();
        {
            const int rr = tid >> 1;
            const int cp = tid & 1;
            const int gi2 = bi * BM + rr;
            const int gj0 = bj * BN + cp * 64;
            float es = 0.f;
            #pragma unroll
            for (int j = 0; j < 64; j += 4) {
                float v0 = stage2[rr * 129 + cp * 64 + j];
                float v1 = stage2[rr * 129 + cp * 64 + j + 1];
                float v2 = stage2[rr * 129 + cp * 64 + j + 2];
                float v3 = stage2[rr * 129 + cp * 64 + j + 3];
                float e0 = __expf(v0);
                float e1 = __expf(v1);
                float e2 = __expf(v2);
                float e3 = __expf(v3);
                if (gi2 == gj0 + j)     e0 = 0.f;
                if (gi2 == gj0 + j + 1) e1 = 0.f;
                if (gi2 == gj0 + j + 2) e2 = 0.f;
                if (gi2 == gj0 + j + 3) e3 = 0.f;
                es += (e0 + e1) + (e2 + e3);
                stage2[rr * 129 + cp * 64 + j]     = e0;
                stage2[rr * 129 + cp * 64 + j + 1] = e1;
                stage2[rr * 129 + cp * 64 + j + 2] = e2;
                stage2[rr * 129 + cp * 64 + j + 3] = e3;
                bstage[rr * 33 + cp * 16 + (j >> 2)] = pack_fp8x4(v0, v1, v2, v3);
            }
            spart[rr][cp * 2] = es;
            spart[rr][cp * 2 + 1] = 0.f;
        }
        __syncthreads();
        epilogue_store_and_cols_full(stage2, bstage, scolp, simb, bi, bj, tid);
        __syncthreads();
        if (tid < 128) {
            float rsum = spart[tid][0] + spart[tid][1] + spart[tid][2] + spart[tid][3];
            dpart[(size_t)(bi * BM + tid) * NBJ + bj] = rsum;
            if (bi != bj) {
                float csum = scolp[tid][0] + scolp[tid][1];
                dpart[(size_t)(bj * BN + tid) * NBJ + bi] = csum;
            }
        }
        __syncthreads();
    }
#endif
}

// ---------------------------------------------------------------------------
// Per-row loss constants: one warp per row, both matrices.
//   g_EF[row] = {E3, F}, E3 = 1/den_t^3, F = E3*(Lo - Lt)
// ---------------------------------------------------------------------------
__global__ void logdenom_kernel() {
    const int row  = blockIdx.x * 8 + (threadIdx.x >> 5);
    const int lane = threadIdx.x & 31;
    const float* dp0 = g_dpart[0] + (size_t)row * NBJ;
    const float* dp1 = g_dpart[1] + (size_t)row * NBJ;
    float v0 = dp0[lane] + dp0[lane + 32];
    float v1 = dp1[lane] + dp1[lane + 32];
    #pragma unroll
    for (int o = 16; o; o >>= 1) {
        v0 += __shfl_xor_sync(0xffffffffu, v0, o);
        v1 += __shfl_xor_sync(0xffffffffu, v1, o);
    }
    if (lane == 0) {
        float Lo = logf(v0);
        float Lt = logf(v1);
        float E3 = 1.0f / (v1 * v1 * v1);
        g_EF[row] = make_float2(E3, E3 * (Lo - Lt));
    }
}

// ---------------------------------------------------------------------------
// 16-element loss group (fp8 inputs). half2 SIMD front-end, vectorized EF LDS.
// ---------------------------------------------------------------------------
__device__ __forceinline__ void loss_group16(
    uint4 qt, uint4 qo,
    float E3i, float Fi, const float2* sEF_j, int c16,
    float& acc0, float& acc1)
{
    const uint16_t* pt = (const uint16_t*)&qt;
    const uint16_t* po = (const uint16_t*)&qo;
    const __half2 c3 = __float2half2_rn(EXP3_LOG2E);
    #pragma unroll
    for (int w = 0; w < 8; w++) {
        __half2 th = fp8x2_to_half2(pt[w]);
        __half2 oh = fp8x2_to_half2(po[w]);
        __half2 dh = __hsub2(th, oh);
        __half2 ah = __hmul2(th, c3);
        float2 d = __half22float2(dh);
        float2 a = __half22float2(ah);
        float ex0 = ex2f(a.x);
        float ex1 = ex2f(a.y);
        float4 ef = *(const float4*)(sEF_j + c16 + w * 2);  // {E3_u,F_u,E3_u1,F_u1}
        float t0 = fmaf(E3i, d.x, Fi) + fmaf(ef.x, d.x, ef.y);
        float t1 = fmaf(E3i, d.y, Fi) + fmaf(ef.z, d.y, ef.w);
        acc0 += ex0 * t0;
        acc1 += ex1 * t1;
    }
}

// ---------------------------------------------------------------------------
// Loss pass: upper-tri tiles; sim(i,j) yields term(i,j) AND term(j,i).
// ---------------------------------------------------------------------------
__global__ void __launch_bounds__(256) loss_kernel() {
    __shared__ __align__(16) float2 sEF_i[128], sEF_j[128];

    int bi, bj;
    tri_decode(blockIdx.x, bi, bj);
    const int tid = threadIdx.x;

    if (tid < 128) {
        sEF_i[tid] = g_EF[bi * BM + tid];
    } else {
        int u = tid - 128;
        sEF_j[u] = g_EF[bj * BN + u];
    }
    __syncthreads();

    const __nv_fp8_e4m3* so = g_sim8_o + (size_t)(bi * BM) * N + (size_t)bj * BN;
    const __nv_fp8_e4m3* st = g_sim8_t + (size_t)(bi * BM) * N + (size_t)bj * BN;

    float acc0 = 0.f, acc1 = 0.f;

    if (bi != bj) {
        #pragma unroll
        for (int it = 0; it < 2; it++) {
            const int p0 = it * 512 + tid;
            const int p1 = p0 + 256;
            const int r0 = p0 >> 3, c0 = (p0 & 7) * 16;
            const int r1 = p1 >> 3, c1 = (p1 & 7) * 16;
            uint4 a0 = *(const uint4*)(st + (size_t)r0 * N + c0);
            uint4 a1 = *(const uint4*)(so + (size_t)r0 * N + c0);
            uint4 b0 = *(const uint4*)(st + (size_t)r1 * N + c1);
            uint4 b1 = *(const uint4*)(so + (size_t)r1 * N + c1);
            float2 efi0 = sEF_i[r0];
            float2 efi1 = sEF_i[r1];

            loss_group16(a0, a1, efi0.x, efi0.y, sEF_j, c0, acc0, acc1);
            loss_group16(b0, b1, efi1.x, efi1.y, sEF_j, c1, acc0, acc1);
        }
    } else {
        for (int p = tid; p < 2048; p += 256) {
            const int r  = p >> 4;
            const int c8 = (p & 15) * 8;
            uint2 qt = *(const uint2*)(st + (size_t)r * N + c8);
            uint2 qo = *(const uint2*)(so + (size_t)r * N + c8);
            const float2 efi = sEF_i[r];

            float stf[8], sof[8];
            {
                const uint16_t* pt = (const uint16_t*)&qt;
                const uint16_t* po = (const uint16_t*)&qo;
                #pragma unroll
                for (int w = 0; w < 4; w++) {
                    float2 ft = fp8x2_to_float2(pt[w]);
                    float2 fo = fp8x2_to_float2(po[w]);
                    stf[w * 2] = ft.x; stf[w * 2 + 1] = ft.y;
                    sof[w * 2] = fo.x; sof[w * 2 + 1] = fo.y;
                }
            }
            #pragma unroll
            for (int u = 0; u < 8; u++) {
                const float keep = (c8 + u > r) ? 1.f : 0.f;
                float d  = stf[u] - sof[u];
                float ex = ex2f(stf[u] * EXP3_LOG2E);
                float2 efj = sEF_j[c8 + u];
                float t  = fmaf(efi.x, d, efi.y) + fmaf(efj.x, d, efj.y);
                acc0 += keep * ex * t;
            }
        }
    }

    float acc = acc0 + acc1;
    #pragma unroll
    for (int o = 16; o; o >>= 1) acc += __shfl_xor_sync(0xffffffffu, acc, o);
    __shared__ float sw[8];
    if ((tid & 31) == 0) sw[tid >> 5] = acc;
    __syncthreads();
    if (tid == 0) {
        float s = 0.f;
        #pragma unroll
        for (int w = 0; w < 8; w++) s += sw[w];
        g_losspart[blockIdx.x] = s;
    }
}

__global__ void final_kernel(float* out) {
    float acc = 0.f;
    for (int k = threadIdx.x; k < NT; k += 256) acc += g_losspart[k];
    #pragma unroll
    for (int o = 16; o; o >>= 1) acc += __shfl_xor_sync(0xffffffffu, acc, o);
    __shared__ float sw[8];
    if ((threadIdx.x & 31) == 0) sw[threadIdx.x >> 5] = acc;
    __syncthreads();
    if (threadIdx.x == 0) {
        float t = 0.f;
        #pragma unroll
        for (int w = 0; w < 8; w++) t += sw[w];
        out[0] = t * (1.0f / ((float)N * (float)N));
    }
}

// ---------------------------------------------------------------------------
// Launch (graph-capturable)
// ---------------------------------------------------------------------------
extern "C" void kernel_launch(void* const* d_in, const int* in_sizes, int n_in,
                              void* d_out, int out_size) {
    const float* mo = (const float*)d_in[0];
    const float* tg = (const float*)d_in[1];
    float* out = (float*)d_out;

    const int dsm = 2 * 49152 + 1024;   // 2 stages x (A+B1+B2); epilogue overlays
    cudaFuncSetAttribute(gemm_tc_kernel, cudaFuncAttributeMaxDynamicSharedMemorySize, dsm);

    normalize_kernel<<<2 * N / 8, 256>>>(mo, tg);

    gemm_tc_kernel<<<2 * NP, 256, dsm>>>();

    logdenom_kernel<<<N / 8, 256>>>();

    loss_kernel<<<NT, 256>>>();
    final_kernel<<<1, 256>>>(out);
}

// round 17
// speedup vs baseline: 1.0389x; 1.0389x over previous
#include <cuda_runtime.h>
#include <cuda_bf16.h>
#include <cuda_fp16.h>
#include <cuda_fp8.h>
#include <math.h>
#include <stdint.h>

// Problem constants
#define N    8192
#define D_O  512
#define D_T  768

#define BM 128
#define BN 128
#define NBJ (N / BN)                 // 64 column-blocks
#define NT  (NBJ * (NBJ + 1) / 2)    // 2080 upper-tri tiles
#define NP  1056                     // sum over bi of ceil((64-bi)/2): tile PAIRS

// Arch-specific (sm_103a) feature gate: tcgen05 PTX only legal at compute_103a.
#if defined(__CUDA_ARCH__) && defined(__CUDA_ARCH_FEAT_SM103_ALL)
#define USE_TCGEN05 1
#else
#define USE_TCGEN05 0
#endif

#define SMEM_SWIZZLE_128B(b) ((b) ^ (((b) >> 3) & 0x70))

// ---------------------------------------------------------------------------
// Common helpers
// ---------------------------------------------------------------------------
__device__ __forceinline__ uint32_t smem_to_u32(const void* p) {
    uint32_t a;
    asm("{ .reg .u64 t; cvta.to.shared.u64 t, %1; cvt.u32.u64 %0, t; }" : "=r"(a) : "l"(p));
    return a;
}
__device__ __forceinline__ uint32_t pack_fp8x4(float v0, float v1, float v2, float v3) {
    __nv_fp8x2_storage_t lo = __nv_cvt_float2_to_fp8x2(make_float2(v0, v1),
                                                       __NV_SATFINITE, __NV_E4M3);
    __nv_fp8x2_storage_t hi = __nv_cvt_float2_to_fp8x2(make_float2(v2, v3),
                                                       __NV_SATFINITE, __NV_E4M3);
    return (uint32_t)lo | ((uint32_t)hi << 16);
}
__device__ __forceinline__ float2 fp8x2_to_float2(uint16_t v) {
    __half2_raw h2 = __nv_cvt_fp8x2_to_halfraw2((__nv_fp8x2_storage_t)v, __NV_E4M3);
    return __half22float2(*reinterpret_cast<__half2*>(&h2));
}
__device__ __forceinline__ __half2 fp8x2_to_half2(uint16_t v) {
    __half2_raw h2 = __nv_cvt_fp8x2_to_halfraw2((__nv_fp8x2_storage_t)v, __NV_E4M3);
    return *reinterpret_cast<__half2*>(&h2);
}
__device__ __forceinline__ float ex2f(float x) {
    float r;
    asm("ex2.approx.f32 %0, %1;" : "=f"(r) : "f"(x));
    return r;
}
#define EXP3_LOG2E 4.328085122666891f   // 3 * log2(e)

#define CP_ASYNC16(sa, ga) \
    asm volatile("cp.async.cg.shared.global [%0], [%1], 16;" :: "r"(sa), "l"(ga))
#define CP_COMMIT() asm volatile("cp.async.commit_group;" ::: "memory")
#define CP_WAIT(n)  asm volatile("cp.async.wait_group %0;" :: "n"(n) : "memory")

#if USE_TCGEN05
__device__ __forceinline__ uint32_t elect_one_pred() {
    uint32_t pred;
    asm volatile(
        "{\n\t.reg .pred p;\n\telect.sync _|p, 0xFFFFFFFF;\n\tselp.b32 %0, 1, 0, p;\n\t}"
        : "=r"(pred));
    return pred;
}

#define TCGEN05_ALLOC(smem_result_addr, nCols) \
    asm volatile("tcgen05.alloc.cta_group::1.sync.aligned.shared::cta.b32 [%0], %1;" \
        :: "r"((uint32_t)(smem_result_addr)), "r"((uint32_t)(nCols)) : "memory")
#define TCGEN05_DEALLOC(tmem_addr, nCols) \
    asm volatile("tcgen05.dealloc.cta_group::1.sync.aligned.b32 %0, %1;" \
        :: "r"(tmem_addr), "r"((uint32_t)(nCols)))
#define TCGEN05_RELINQUISH() \
    asm volatile("tcgen05.relinquish_alloc_permit.cta_group::1.sync.aligned;")
#define TCGEN05_COMMIT(mbar_smem_addr) \
    asm volatile("tcgen05.commit.cta_group::1.mbarrier::arrive::one.shared::cluster.b64 [%0];" \
        :: "r"((uint32_t)(mbar_smem_addr)) : "memory")
#define TCGEN05_FENCE_AFTER() \
    asm volatile("tcgen05.fence::after_thread_sync;" ::: "memory")
#define TCGEN05_WAIT_LD() \
    asm volatile("tcgen05.wait::ld.sync.aligned;" ::: "memory")
#define FENCE_PROXY_ASYNC_SHARED_CTA() \
    asm volatile("fence.proxy.async.shared::cta;" ::: "memory")
#define MBARRIER_INIT(mbar, count) \
    asm volatile("mbarrier.init.shared.b64 [%0], %1;" \
        :: "r"((uint32_t)(mbar)), "r"((uint32_t)(count)) : "memory")
#define MBARRIER_INVAL(mbar) \
    asm volatile("mbarrier.inval.shared.b64 [%0];" :: "r"((uint32_t)(mbar)) : "memory")

#define MBARRIER_WAIT_PARITY(mbar_smem_addr, phase_parity) do { \
    uint32_t _mbar = (uint32_t)(mbar_smem_addr); \
    uint32_t _parity = (uint32_t)(phase_parity); \
    uint32_t _done; \
    asm volatile( \
        "{\n\t.reg .pred p;\n\t" \
        "mbarrier.try_wait.parity.acquire.cta.shared::cta.b64 p, [%1], %2;\n\t" \
        "selp.b32 %0, 1, 0, p;\n\t}" \
        : "=r"(_done) : "r"(_mbar), "r"(_parity) : "memory"); \
    if (!_done) { \
        asm volatile( \
            "{\n\t.reg .pred P1;\n\t" \
            "WAIT_LOOP_%=:\n\t" \
            "mbarrier.try_wait.parity.acquire.cta.shared::cta.b64 P1, [%0], %1, 0x989680;\n\t" \
            "@P1 bra.uni WAIT_DONE_%=;\n\t" \
            "bra.uni WAIT_LOOP_%=;\n\t" \
            "WAIT_DONE_%=:\n\t}" \
            :: "r"(_mbar), "r"(_parity) : "memory"); \
    } \
} while(0)

#define TCGEN05_LD_32X32B_X32(r, tmem_addr) \
    asm volatile( \
        "tcgen05.ld.sync.aligned.32x32b.x32.b32 " \
        "{%0, %1, %2, %3, %4, %5, %6, %7, " \
        " %8, %9, %10, %11, %12, %13, %14, %15, " \
        " %16, %17, %18, %19, %20, %21, %22, %23, " \
        " %24, %25, %26, %27, %28, %29, %30, %31}, [%32];" \
        : "=r"((r)[0]),  "=r"((r)[1]),  "=r"((r)[2]),  "=r"((r)[3]), \
          "=r"((r)[4]),  "=r"((r)[5]),  "=r"((r)[6]),  "=r"((r)[7]), \
          "=r"((r)[8]),  "=r"((r)[9]),  "=r"((r)[10]), "=r"((r)[11]), \
          "=r"((r)[12]), "=r"((r)[13]), "=r"((r)[14]), "=r"((r)[15]), \
          "=r"((r)[16]), "=r"((r)[17]), "=r"((r)[18]), "=r"((r)[19]), \
          "=r"((r)[20]), "=r"((r)[21]), "=r"((r)[22]), "=r"((r)[23]), \
          "=r"((r)[24]), "=r"((r)[25]), "=r"((r)[26]), "=r"((r)[27]), \
          "=r"((r)[28]), "=r"((r)[29]), "=r"((r)[30]), "=r"((r)[31]) \
        : "r"(tmem_addr))

// FP8 (e4m3 x e4m3 -> f32) SS MMA, cta_group::1, kind::f8f6f4.
__device__ __forceinline__ void mma_f8_ss_cg1(
    uint32_t d_tmem, uint64_t a_desc, uint64_t b_desc, uint32_t idesc, bool en) {
    uint32_t e = en ? 1 : 0;
    asm volatile(
        "{\n\t.reg .pred p;\n\tsetp.ne.u32 p, %5, 0;\n\t"
        "tcgen05.mma.cta_group::1.kind::f8f6f4 [%0], %1, %2, %3, {%4, %4, %4, %4}, p;\n\t}"
        :: "r"(d_tmem), "l"(a_desc), "l"(b_desc), "r"(idesc), "r"(0u), "r"(e)
        : "memory");
}

static constexpr uint64_t SMEM_DESC_BASE_SW128 =
    (uint64_t(2) << 61) | (uint64_t(1) << 46) | (uint64_t(64) << 32) | (uint64_t(1) << 16);
#define MAKE_SMEM_DESC(base_addr) \
    (SMEM_DESC_BASE_SW128 | ((uint64_t)((base_addr) >> 4) & 0x3FFF))

// idesc: f32 accum (bit4), E4M3 A/B, N=128, M=128
static constexpr uint32_t MMA_IDESC_F8 =
    (1u << 4) | ((128u / 8) << 17) | ((128u / 16) << 24);
#endif // USE_TCGEN05

// Fallback fragment ops (legal PTX at .target sm_103; compile-only safety net)
__device__ __forceinline__ void ldmatrix_x4(uint32_t* r, uint32_t addr) {
    asm volatile("ldmatrix.sync.aligned.m8n8.x4.shared.b16 {%0,%1,%2,%3}, [%4];"
        : "=r"(r[0]), "=r"(r[1]), "=r"(r[2]), "=r"(r[3]) : "r"(addr));
}
__device__ __forceinline__ void mma_16816_bf16(float* c, const uint32_t* a, const uint32_t* b) {
    asm volatile(
        "mma.sync.aligned.m16n8k16.row.col.f32.bf16.bf16.f32 "
        "{%0,%1,%2,%3}, {%4,%5,%6,%7}, {%8,%9}, {%0,%1,%2,%3};"
        : "+f"(c[0]), "+f"(c[1]), "+f"(c[2]), "+f"(c[3])
        : "r"(a[0]), "r"(a[1]), "r"(a[2]), "r"(a[3]), "r"(b[0]), "r"(b[1]));
}

// ---------------------------------------------------------------------------
// Scratch (__device__ globals)
// ---------------------------------------------------------------------------
__device__ __align__(16) __nv_fp8_e4m3 g_x8[N * D_O];             // normalized, e4m3
__device__ __align__(16) __nv_fp8_e4m3 g_t8[N * D_T];
__device__ __align__(16) __nv_fp8_e4m3 g_sim8_o[(size_t)N * N];   // 64 MB, upper-tri
__device__ __align__(16) __nv_fp8_e4m3 g_sim8_t[(size_t)N * N];
__device__ float g_dpart[2][N * NBJ];
__device__ __align__(16) float g_E3[N];   // exp(-3*Lt) = 1/den_t^3
__device__ __align__(16) float g_F[N];    // E3 * (Lo - Lt)
__device__ float g_losspart[NT];

// ---------------------------------------------------------------------------
// Warp-per-row L2-normalize (fp32 math) -> e4m3. 8 rows per 256-thread block.
// ---------------------------------------------------------------------------
__global__ void __launch_bounds__(256) normalize_kernel(
    const float* __restrict__ mo, const float* __restrict__ tg) {
    const int gw    = blockIdx.x * 8 + (threadIdx.x >> 5);
    const int which = (gw >= N);
    const int row   = which ? (gw - N) : gw;
    const int D     = which ? D_T : D_O;
    const int lane  = threadIdx.x & 31;
    const float4* xr4 = (const float4*)((which ? tg : mo) + (size_t)row * D);
    uint32_t* orow = (uint32_t*)((which ? g_t8 : g_x8) + (size_t)row * D);
    const int nseg = D >> 7;

    float4 rv[6];
    float ss = 0.f;
    #pragma unroll 6
    for (int s = 0; s < nseg; s++) {
        float4 v = xr4[lane + s * 32];
        rv[s] = v;
        ss += v.x * v.x + v.y * v.y + v.z * v.z + v.w * v.w;
    }
    #pragma unroll
    for (int o = 16; o; o >>= 1) ss += __shfl_xor_sync(0xffffffffu, ss, o);
    const float sc = 1.0f / fmaxf(sqrtf(ss), 1e-8f);

    #pragma unroll 6
    for (int s = 0; s < nseg; s++) {
        float4 v = rv[s];
        orow[lane + s * 32] = pack_fp8x4(v.x * sc, v.y * sc, v.z * sc, v.w * sc);
    }
}

// ---------------------------------------------------------------------------
// Triangular decode: t -> (bi, bj), bi <= bj
// ---------------------------------------------------------------------------
__device__ __forceinline__ void tri_decode(int t, int& bi, int& bj) {
    int b = (int)(NBJ + 0.5f - sqrtf((NBJ + 0.5f) * (NBJ + 0.5f) - 2.0f * (float)t));
    if (b < 0) b = 0;
    if (b > NBJ - 1) b = NBJ - 1;
    #define TRI_START(x) ((x) * (2 * NBJ - (x) + 1) / 2)
    while (b > 0 && TRI_START(b) > t) b--;
    while (b < NBJ - 1 && TRI_START(b + 1) <= t) b++;
    bi = b;
    bj = b + (t - TRI_START(b));
    #undef TRI_START
}

// Pair decode: p in [0, NP) -> (bi, bj1)
__device__ __forceinline__ void pair_decode(int p, int& bi, int& bj1) {
    int rem = p;
    int b = 0;
    while (true) {
        int cnt = (NBJ - b + 1) >> 1;
        if (rem < cnt) break;
        rem -= cnt;
        b++;
    }
    bi = b;
    bj1 = b + 2 * rem;
}

// ---------------------------------------------------------------------------
// cp.async loaders: 128 rows x 128 e4m3 (16 KB) per matrix per chunk, SW128.
// ---------------------------------------------------------------------------
__device__ __forceinline__ void load_one(
    const __nv_fp8_e4m3* Xb, int D, int c, uint32_t smX, int tid)
{
    #pragma unroll
    for (int s = 0; s < 4; s++) {
        int seg = tid + s * 256;
        int row = seg >> 3;
        int sc  = seg & 7;
        uint32_t off = SMEM_SWIZZLE_128B((uint32_t)(row * 128 + sc * 16));
        CP_ASYNC16(smX + off, Xb + (size_t)row * D + c * 128 + sc * 16);
    }
}
__device__ __forceinline__ void load_three(
    const __nv_fp8_e4m3* Ab, const __nv_fp8_e4m3* B1, const __nv_fp8_e4m3* B2,
    int D, int c, uint32_t smA, uint32_t smB1, uint32_t smB2, bool act2, int tid)
{
    #pragma unroll
    for (int s = 0; s < 4; s++) {
        int seg = tid + s * 256;
        int row = seg >> 3;
        int sc  = seg & 7;
        uint32_t off = SMEM_SWIZZLE_128B((uint32_t)(row * 128 + sc * 16));
        const size_t g = (size_t)row * D + c * 128 + sc * 16;
        CP_ASYNC16(smA + off, Ab + g);
        CP_ASYNC16(smB1 + off, B1 + g);
        if (act2) CP_ASYNC16(smB2 + off, B2 + g);
    }
}

// ---------------------------------------------------------------------------
// Full-tile epilogue store (fp8 sims) + column partials.
// ---------------------------------------------------------------------------
__device__ __forceinline__ void epilogue_store_and_cols_full(
    const float* stage2, const uint32_t* bstage, float (*scolp)[2],
    __nv_fp8_e4m3* simb, int bi, int bj, int tid)
{
    __nv_fp8_e4m3* dst = simb + (size_t)(bi * BM) * N + (size_t)bj * BN;
    #pragma unroll
    for (int p = 0; p < 16; p++) {
        int idx = p * 256 + tid;
        int rr = idx >> 5;
        int cw = idx & 31;
        ((uint32_t*)(dst + (size_t)rr * N))[cw] = bstage[rr * 33 + cw];
    }
    if (bi != bj) {
        const int cc   = tid & 127;
        const int part = tid >> 7;
        float ec = 0.f;
        #pragma unroll 16
        for (int rr = 0; rr < 64; rr++)
            ec += stage2[(part * 64 + rr) * 129 + cc];
        scolp[cc][part] = ec;
    }
}

// ---------------------------------------------------------------------------
// Pair GEMM kernel (FP8): tiles (bi,bj1) and (bi,bj1+1), shared A load,
// 2-stage cp.async pipeline with split commits. Full-tile epilogue.
// ---------------------------------------------------------------------------
__global__ void __launch_bounds__(256, 2) gemm_tc_kernel() {
    const int which = blockIdx.x & 1;
    const int pidx  = blockIdx.x >> 1;
    const int D     = which ? D_T : D_O;
    const int NCH   = D >> 7;
    const __nv_fp8_e4m3* X = which ? g_t8 : g_x8;
    __nv_fp8_e4m3* simb    = which ? g_sim8_t : g_sim8_o;
    float* dpart           = g_dpart[which];

    extern __shared__ char dsm_raw[];
    __shared__ float spart[128][4];
    __shared__ float scolp[128][2];

    const uint32_t raw  = smem_to_u32(dsm_raw);
    const uint32_t base = (raw + 1023u) & ~1023u;
    char* sm = dsm_raw + (base - raw);
    float*    stage2 = (float*)sm;                 // full tile: 128x129 fp32 (66048 B)
    uint32_t* bstage = (uint32_t*)(sm + 66048);    // packed fp8x4: 128x33 u32 (16896 B)

    const int tid = threadIdx.x;
    const int wid = tid >> 5;
    const int lid = tid & 31;

    int bi, bj1;
    pair_decode(pidx, bi, bj1);
    const int bj2 = bj1 + 1;
    const bool act2 = (bj2 < NBJ);

    const __nv_fp8_e4m3* Ab  = X + (size_t)bi  * BM * D;
    const __nv_fp8_e4m3* B1b = X + (size_t)bj1 * BN * D;
    const __nv_fp8_e4m3* B2b = X + (size_t)(act2 ? bj2 : bj1) * BN * D;

#if USE_TCGEN05
    __shared__ uint32_t s_tmem;
    __shared__ __align__(8) uint64_t s_mbar[2][2];

    if (wid == 0) {
        TCGEN05_ALLOC(smem_to_u32(&s_tmem), 256);
        TCGEN05_RELINQUISH();
    }
    if (tid == 0) {
        MBARRIER_INIT(smem_to_u32(&s_mbar[0][0]), 1);
        MBARRIER_INIT(smem_to_u32(&s_mbar[0][1]), 1);
        MBARRIER_INIT(smem_to_u32(&s_mbar[1][0]), 1);
        MBARRIER_INIT(smem_to_u32(&s_mbar[1][1]), 1);
    }
    __syncthreads();
    const uint32_t tmem = s_tmem;

    uint32_t smA[2], smB1[2], smB2[2];
    uint64_t adesc[2], b1desc[2], b2desc[2];
    #pragma unroll
    for (int s = 0; s < 2; s++) {
        smA[s]  = base + s * 49152u;
        smB1[s] = smA[s] + 16384u;
        smB2[s] = smA[s] + 32768u;
        adesc[s]  = MAKE_SMEM_DESC(smA[s]);
        b1desc[s] = MAKE_SMEM_DESC(smB1[s]);
        b2desc[s] = MAKE_SMEM_DESC(smB2[s]);
    }

    load_three(Ab, B1b, B2b, D, 0, smA[0], smB1[0], smB2[0], act2, tid); CP_COMMIT();
    load_three(Ab, B1b, B2b, D, 1, smA[1], smB1[1], smB2[1], act2, tid); CP_COMMIT();

    for (int c = 0; c < NCH; c++) {
        const int b = c & 1;
        if (c + 1 < NCH) CP_WAIT(1);
        else             CP_WAIT(0);
        FENCE_PROXY_ASYNC_SHARED_CTA();
        __syncthreads();

        if (wid == 0 && elect_one_pred()) {
            #pragma unroll
            for (int k = 0; k < 4; k++)
                mma_f8_ss_cg1(tmem, adesc[b] + k * 2, b1desc[b] + k * 2,
                              MMA_IDESC_F8, (c > 0) || (k > 0));
            TCGEN05_COMMIT(smem_to_u32(&s_mbar[b][0]));
            if (act2) {
                #pragma unroll
                for (int k = 0; k < 4; k++)
                    mma_f8_ss_cg1(tmem + 128, adesc[b] + k * 2, b2desc[b] + k * 2,
                                  MMA_IDESC_F8, (c > 0) || (k > 0));
            }
            TCGEN05_COMMIT(smem_to_u32(&s_mbar[b][1]));
        }
        if (c + 2 < NCH) {
            const int ph = (c >> 1) & 1;
            MBARRIER_WAIT_PARITY(smem_to_u32(&s_mbar[b][0]), ph);
            load_one(B1b, D, c + 2, smB1[b], tid);
            MBARRIER_WAIT_PARITY(smem_to_u32(&s_mbar[b][1]), ph);
            load_one(Ab, D, c + 2, smA[b], tid);
            if (act2) load_one(B2b, D, c + 2, smB2[b], tid);
            CP_COMMIT();
        }
    }
    {
        const int cl = NCH - 1;
        const int ph = (cl >> 1) & 1;
        MBARRIER_WAIT_PARITY(smem_to_u32(&s_mbar[cl & 1][1]), ph);
    }
    TCGEN05_FENCE_AFTER();
    __syncthreads();

    // ---- full-tile epilogue ----
    const int sub = wid & 3;
    const int cg  = wid >> 2;
    const int r   = sub * 32 + lid;
    const int gi  = bi * BM + r;

    const int ntile = act2 ? 2 : 1;
    for (int tt = 0; tt < ntile; tt++) {
        const int bj = bj1 + tt;
        const bool odg = (bi != bj);
        #pragma unroll
        for (int h = 0; h < 2; h++) {
            uint32_t dreg[32];
            TCGEN05_LD_32X32B_X32(dreg, tmem + tt * 128 + h * 64 + cg * 32);
            TCGEN05_WAIT_LD();

            const int c0  = h * 64 + cg * 32;
            const int gj0 = bj * BN + c0;
            float rs = 0.f;
            #pragma unroll
            for (int j = 0; j < 32; j += 4) {
                float v0 = __uint_as_float(dreg[j]);
                float v1 = __uint_as_float(dreg[j + 1]);
                float v2 = __uint_as_float(dreg[j + 2]);
                float v3 = __uint_as_float(dreg[j + 3]);
                float e0 = __expf(v0);
                float e1 = __expf(v1);
                float e2 = __expf(v2);
                float e3 = __expf(v3);
                if (gi == gj0 + j)     e0 = 0.f;
                if (gi == gj0 + j + 1) e1 = 0.f;
                if (gi == gj0 + j + 2) e2 = 0.f;
                if (gi == gj0 + j + 3) e3 = 0.f;
                rs += (e0 + e1) + (e2 + e3);
                if (odg) {
                    stage2[r * 129 + c0 + j]     = e0;
                    stage2[r * 129 + c0 + j + 1] = e1;
                    stage2[r * 129 + c0 + j + 2] = e2;
                    stage2[r * 129 + c0 + j + 3] = e3;
                }
                bstage[r * 33 + (c0 >> 2) + (j >> 2)] = pack_fp8x4(v0, v1, v2, v3);
            }
            spart[r][h * 2 + cg] = rs;
        }
        __syncthreads();

        epilogue_store_and_cols_full(stage2, bstage, scolp, simb, bi, bj, tid);
        __syncthreads();

        if (tid < 128) {
            float rsum = spart[tid][0] + spart[tid][1] + spart[tid][2] + spart[tid][3];
            dpart[(size_t)(bi * BM + tid) * NBJ + bj] = rsum;
            if (odg) {
                float csum = scolp[tid][0] + scolp[tid][1];
                dpart[(size_t)(bj * BN + tid) * NBJ + bi] = csum;
            }
        }
        __syncthreads();
    }

    if (tid == 0) {
        MBARRIER_INVAL(smem_to_u32(&s_mbar[0][0]));
        MBARRIER_INVAL(smem_to_u32(&s_mbar[0][1]));
        MBARRIER_INVAL(smem_to_u32(&s_mbar[1][0]));
        MBARRIER_INVAL(smem_to_u32(&s_mbar[1][1]));
    }
    __syncthreads();
    if (wid == 0) TCGEN05_DEALLOC(tmem, 256);
#else
    // ================= mma.sync fallback (compile-only safety net) =========
    const uint32_t smA0 = base;
    const uint32_t smB0 = base + 16384u;
    char* smc = sm;
    const int warp_m = wid & 3;
    const int warp_n = wid >> 2;
    const int NCH2 = D >> 6;

    const int ntile = act2 ? 2 : 1;
    for (int tt = 0; tt < ntile; tt++) {
        const int bj = bj1 + tt;
        const __nv_fp8_e4m3* Bb = X + (size_t)bj * BN * D;

        float c[2][8][4];
        #pragma unroll
        for (int mt = 0; mt < 2; mt++)
            #pragma unroll
            for (int nt = 0; nt < 8; nt++)
                #pragma unroll
                for (int q = 0; q < 4; q++) c[mt][nt][q] = 0.f;

        for (int ch = 0; ch < NCH2; ch++) {
            #pragma unroll
            for (int s = 0; s < 4; s++) {
                int seg = tid + s * 256;
                int row = seg >> 3;
                int sc  = seg & 7;
                const __nv_fp8_e4m3* pa = Ab + (size_t)row * D + ch * 64 + sc * 8;
                const __nv_fp8_e4m3* pb = Bb + (size_t)row * D + ch * 64 + sc * 8;
                __nv_bfloat16 at[8], bt[8];
                #pragma unroll
                for (int i = 0; i < 8; i++) {
                    at[i] = __float2bfloat16((float)pa[i]);
                    bt[i] = __float2bfloat16((float)pb[i]);
                }
                uint32_t off = SMEM_SWIZZLE_128B((uint32_t)(row * 128 + sc * 16));
                *(uint4*)(smc + off)         = *(uint4*)at;
                *(uint4*)(smc + 16384 + off) = *(uint4*)bt;
            }
            __syncthreads();

            #pragma unroll
            for (int ks = 0; ks < 4; ks++) {
                uint32_t a[2][4];
                #pragma unroll
                for (int mt = 0; mt < 2; mt++) {
                    int row  = warp_m * 32 + mt * 16 + (lid & 15);
                    int boff = ks * 32 + (lid >> 4) * 16;
                    ldmatrix_x4(a[mt], smA0 + SMEM_SWIZZLE_128B((uint32_t)(row * 128 + boff)));
                }
                uint32_t b[8][2];
                #pragma unroll
                for (int np = 0; np < 4; np++) {
                    int mat = lid >> 3;
                    int nt  = np * 2 + (mat >> 1);
                    int kh  = mat & 1;
                    int row  = warp_n * 64 + nt * 8 + (lid & 7);
                    int boff = ks * 32 + kh * 16;
                    uint32_t r4[4];
                    ldmatrix_x4(r4, smB0 + SMEM_SWIZZLE_128B((uint32_t)(row * 128 + boff)));
                    b[np * 2][0]     = r4[0];
                    b[np * 2][1]     = r4[1];
                    b[np * 2 + 1][0] = r4[2];
                    b[np * 2 + 1][1] = r4[3];
                }
                #pragma unroll
                for (int mt = 0; mt < 2; mt++)
                    #pragma unroll
                    for (int nt = 0; nt < 8; nt++)
                        mma_16816_bf16(c[mt][nt], a[mt], b[nt]);
            }
            __syncthreads();
        }

        #pragma unroll
        for (int mt = 0; mt < 2; mt++)
            #pragma unroll
            for (int nt = 0; nt < 8; nt++) {
                int r0  = warp_m * 32 + mt * 16 + (lid >> 2);
                int col = warp_n * 64 + nt * 8 + (lid & 3) * 2;
                stage2[r0 * 129 + col]           = c[mt][nt][0];
                stage2[r0 * 129 + col + 1]       = c[mt][nt][1];
                stage2[(r0 + 8) * 129 + col]     = c[mt][nt][2];
                stage2[(r0 + 8) * 129 + col + 1] = c[mt][nt][3];
            }
        __syncthreads();
        {
            const int rr = tid >> 1;
            const int cp = tid & 1;
            const int gi2 = bi * BM + rr;
            const int gj0 = bj * BN + cp * 64;
            float es = 0.f;
            #pragma unroll
            for (int j = 0; j < 64; j += 4) {
                float v0 = stage2[rr * 129 + cp * 64 + j];
                float v1 = stage2[rr * 129 + cp * 64 + j + 1];
                float v2 = stage2[rr * 129 + cp * 64 + j + 2];
                float v3 = stage2[rr * 129 + cp * 64 + j + 3];
                float e0 = __expf(v0);
                float e1 = __expf(v1);
                float e2 = __expf(v2);
                float e3 = __expf(v3);
                if (gi2 == gj0 + j)     e0 = 0.f;
                if (gi2 == gj0 + j + 1) e1 = 0.f;
                if (gi2 == gj0 + j + 2) e2 = 0.f;
                if (gi2 == gj0 + j + 3) e3 = 0.f;
                es += (e0 + e1) + (e2 + e3);
                stage2[rr * 129 + cp * 64 + j]     = e0;
                stage2[rr * 129 + cp * 64 + j + 1] = e1;
                stage2[rr * 129 + cp * 64 + j + 2] = e2;
                stage2[rr * 129 + cp * 64 + j + 3] = e3;
                bstage[rr * 33 + cp * 16 + (j >> 2)] = pack_fp8x4(v0, v1, v2, v3);
            }
            spart[rr][cp * 2] = es;
            spart[rr][cp * 2 + 1] = 0.f;
        }
        __syncthreads();
        epilogue_store_and_cols_full(stage2, bstage, scolp, simb, bi, bj, tid);
        __syncthreads();
        if (tid < 128) {
            float rsum = spart[tid][0] + spart[tid][1] + spart[tid][2] + spart[tid][3];
            dpart[(size_t)(bi * BM + tid) * NBJ + bj] = rsum;
            if (bi != bj) {
                float csum = scolp[tid][0] + scolp[tid][1];
                dpart[(size_t)(bj * BN + tid) * NBJ + bi] = csum;
            }
        }
        __syncthreads();
    }
#endif
}

// ---------------------------------------------------------------------------
// Per-row loss constants: one warp per row, both matrices.
// ---------------------------------------------------------------------------
__global__ void logdenom_kernel() {
    const int row  = blockIdx.x * 8 + (threadIdx.x >> 5);
    const int lane = threadIdx.x & 31;
    const float* dp0 = g_dpart[0] + (size_t)row * NBJ;
    const float* dp1 = g_dpart[1] + (size_t)row * NBJ;
    float v0 = dp0[lane] + dp0[lane + 32];
    float v1 = dp1[lane] + dp1[lane + 32];
    #pragma unroll
    for (int o = 16; o; o >>= 1) {
        v0 += __shfl_xor_sync(0xffffffffu, v0, o);
        v1 += __shfl_xor_sync(0xffffffffu, v1, o);
    }
    if (lane == 0) {
        float Lo = logf(v0);
        float Lt = logf(v1);
        float E3 = 1.0f / (v1 * v1 * v1);
        g_E3[row] = E3;
        g_F[row]  = E3 * (Lo - Lt);
    }
}

// ---------------------------------------------------------------------------
// 16-element loss group (fp8 inputs). half2 arithmetic front-end +
// split scalar E3/F LDS (64B lane stride -> low conflict).
// ---------------------------------------------------------------------------
__device__ __forceinline__ void loss_group16(
    uint4 qt, uint4 qo,
    float E3i, float Fi, const float* sE3_j, const float* sF_j, int c16,
    float& acc0, float& acc1)
{
    const uint16_t* pt = (const uint16_t*)&qt;
    const uint16_t* po = (const uint16_t*)&qo;
    const __half2 c3 = __float2half2_rn(EXP3_LOG2E);
    #pragma unroll
    for (int w = 0; w < 8; w++) {
        __half2 th = fp8x2_to_half2(pt[w]);
        __half2 oh = fp8x2_to_half2(po[w]);
        __half2 dh = __hsub2(th, oh);
        __half2 ah = __hmul2(th, c3);
        float2 d = __half22float2(dh);
        float2 a = __half22float2(ah);
        float ex0 = ex2f(a.x);
        float ex1 = ex2f(a.y);
        const int u = c16 + w * 2;
        float t0 = fmaf(E3i, d.x, Fi) + fmaf(sE3_j[u], d.x, sF_j[u]);
        float t1 = fmaf(E3i, d.y, Fi) + fmaf(sE3_j[u + 1], d.y, sF_j[u + 1]);
        acc0 += ex0 * t0;
        acc1 += ex1 * t1;
    }
}

// ---------------------------------------------------------------------------
// Loss pass: upper-tri tiles; sim(i,j) yields term(i,j) AND term(j,i).
// ---------------------------------------------------------------------------
__global__ void __launch_bounds__(256) loss_kernel() {
    __shared__ __align__(16) float sE3_i[128], sF_i[128], sE3_j[128], sF_j[128];

    int bi, bj;
    tri_decode(blockIdx.x, bi, bj);
    const int tid = threadIdx.x;

    if (tid < 128) {
        sE3_i[tid] = g_E3[bi * BM + tid];
        sF_i[tid]  = g_F[bi * BM + tid];
    } else {
        int u = tid - 128;
        sE3_j[u] = g_E3[bj * BN + u];
        sF_j[u]  = g_F[bj * BN + u];
    }
    __syncthreads();

    const __nv_fp8_e4m3* so = g_sim8_o + (size_t)(bi * BM) * N + (size_t)bj * BN;
    const __nv_fp8_e4m3* st = g_sim8_t + (size_t)(bi * BM) * N + (size_t)bj * BN;

    float acc0 = 0.f, acc1 = 0.f;

    if (bi != bj) {
        #pragma unroll
        for (int it = 0; it < 2; it++) {
            const int p0 = it * 512 + tid;
            const int p1 = p0 + 256;
            const int r0 = p0 >> 3, c0 = (p0 & 7) * 16;
            const int r1 = p1 >> 3, c1 = (p1 & 7) * 16;
            uint4 a0 = *(const uint4*)(st + (size_t)r0 * N + c0);
            uint4 a1 = *(const uint4*)(so + (size_t)r0 * N + c0);
            uint4 b0 = *(const uint4*)(st + (size_t)r1 * N + c1);
            uint4 b1 = *(const uint4*)(so + (size_t)r1 * N + c1);

            loss_group16(a0, a1, sE3_i[r0], sF_i[r0], sE3_j, sF_j, c0, acc0, acc1);
            loss_group16(b0, b1, sE3_i[r1], sF_i[r1], sE3_j, sF_j, c1, acc0, acc1);
        }
    } else {
        for (int p = tid; p < 2048; p += 256) {
            const int r  = p >> 4;
            const int c8 = (p & 15) * 8;
            uint2 qt = *(const uint2*)(st + (size_t)r * N + c8);
            uint2 qo = *(const uint2*)(so + (size_t)r * N + c8);
            const float E3i = sE3_i[r], Fi = sF_i[r];

            float stf[8], sof[8];
            {
                const uint16_t* pt = (const uint16_t*)&qt;
                const uint16_t* po = (const uint16_t*)&qo;
                #pragma unroll
                for (int w = 0; w < 4; w++) {
                    float2 ft = fp8x2_to_float2(pt[w]);
                    float2 fo = fp8x2_to_float2(po[w]);
                    stf[w * 2] = ft.x; stf[w * 2 + 1] = ft.y;
                    sof[w * 2] = fo.x; sof[w * 2 + 1] = fo.y;
                }
            }
            #pragma unroll
            for (int u = 0; u < 8; u++) {
                const float keep = (c8 + u > r) ? 1.f : 0.f;
                float d  = stf[u] - sof[u];
                float ex = ex2f(stf[u] * EXP3_LOG2E);
                float t  = fmaf(E3i, d, Fi) + fmaf(sE3_j[c8 + u], d, sF_j[c8 + u]);
                acc0 += keep * ex * t;
            }
        }
    }

    float acc = acc0 + acc1;
    #pragma unroll
    for (int o = 16; o; o >>= 1) acc += __shfl_xor_sync(0xffffffffu, acc, o);
    __shared__ float sw[8];
    if ((tid & 31) == 0) sw[tid >> 5] = acc;
    __syncthreads();
    if (tid == 0) {
        float s = 0.f;
        #pragma unroll
        for (int w = 0; w < 8; w++) s += sw[w];
        g_losspart[blockIdx.x] = s;
    }
}

__global__ void final_kernel(float* out) {
    float acc = 0.f;
    for (int k = threadIdx.x; k < NT; k += 256) acc += g_losspart[k];
    #pragma unroll
    for (int o = 16; o; o >>= 1) acc += __shfl_xor_sync(0xffffffffu, acc, o);
    __shared__ float sw[8];
    if ((threadIdx.x & 31) == 0) sw[threadIdx.x >> 5] = acc;
    __syncthreads();
    if (threadIdx.x == 0) {
        float t = 0.f;
        #pragma unroll
        for (int w = 0; w < 8; w++) t += sw[w];
        out[0] = t * (1.0f / ((float)N * (float)N));
    }
}

// ---------------------------------------------------------------------------
// Launch (graph-capturable)
// ---------------------------------------------------------------------------
extern "C" void kernel_launch(void* const* d_in, const int* in_sizes, int n_in,
                              void* d_out, int out_size) {
    const float* mo = (const float*)d_in[0];
    const float* tg = (const float*)d_in[1];
    float* out = (float*)d_out;

    const int dsm = 2 * 49152 + 1024;   // 2 stages x (A+B1+B2); epilogue overlays
    cudaFuncSetAttribute(gemm_tc_kernel, cudaFuncAttributeMaxDynamicSharedMemorySize, dsm);

    normalize_kernel<<<2 * N / 8, 256>>>(mo, tg);

    gemm_tc_kernel<<<2 * NP, 256, dsm>>>();

    logdenom_kernel<<<N / 8, 256>>>();

    loss_kernel<<<NT, 256>>>();
    final_kernel<<<1, 256>>>(out);
}